// round 3
// baseline (speedup 1.0000x reference)
#include <cuda_runtime.h>
#include <cuda_bf16.h>
#include <math.h>

// Problem constants
#define V_    50000
#define IN_   300
#define M_    150
#define G3_   450      // 3*M
#define NL_   200000
#define D_    6
#define N_    40000
#define K_    4
#define B_    64
#define S_    64
#define NCTX  (B_*S_)          // 4096
#define NJOB  (NCTX*5)         // 20480: slot e*5+0 = direct leaf, e*5+1..4 = children

#define TB 8   // leaf jobs per block
#define TC 8   // ctx elements per dep block

// Scratch (device globals — no allocation allowed)
__device__ int   g_job[NJOB];          // leaf index (0..NL-1) or -1
__device__ int   g_type[NCTX];         // 0=zero slot, 1=leaf, 2=dep
__device__ int   g_word[NCTX];         // word idx for dep elements
__device__ float g_c[(size_t)NJOB * M_];
__device__ float g_h[(size_t)NJOB * M_];

__device__ __forceinline__ float sigm(float x) { return 1.0f / (1.0f + expf(-x)); }

// ---------------------------------------------------------------------------
// Kernel A: classify each ctx element, build the leaf-job list
// ---------------------------------------------------------------------------
__global__ void build_jobs_kernel(const int* __restrict__ ctx,
                                  const int* __restrict__ dep_word,
                                  const int* __restrict__ dep_child) {
    int e = blockIdx.x * blockDim.x + threadIdx.x;
    if (e >= NCTX) return;
    int s = ctx[e];
    int base = e * 5;
    int j[5] = {-1, -1, -1, -1, -1};
    int type = 0, word = 0;
    if (s == 0) {
        type = 0;
    } else if (s <= NL_) {
        type = 1;
        j[0] = s - 1;
    } else {
        type = 2;
        int node = s - 1 - NL_;          // 0 .. D*N-1 (layer-major, matches [D,N] flat)
        word = dep_word[node];
        #pragma unroll
        for (int k = 0; k < K_; k++) {
            int cs = dep_child[node * K_ + k];   // slot in [1, 1+NL)
            j[1 + k] = (cs >= 1 && cs <= NL_) ? (cs - 1) : -1;
        }
    }
    #pragma unroll
    for (int q = 0; q < 5; q++) g_job[base + q] = j[q];
    g_type[e] = type;
    g_word[e] = word;
}

// ---------------------------------------------------------------------------
// Kernel B: leaf cell for every job slot.
// Block handles TB=8 jobs; 150 compute threads, one per M-lane, 3 gates each.
// W_leaf columns are read once per block (L2-resident), x rows live in SMEM.
// ---------------------------------------------------------------------------
__global__ void __launch_bounds__(160, 4)
leaf_kernel(const float* __restrict__ embed,
            const float* __restrict__ Wl,
            const float* __restrict__ bl,
            const int*   __restrict__ leaf_idx) {
    __shared__ float sx[TB * IN_];     // 9600 floats
    __shared__ int   sjob[TB];
    __shared__ int   sword[TB];

    const int jb  = blockIdx.x * TB;
    const int tid = threadIdx.x;

    if (tid < TB) {
        int j = g_job[jb + tid];
        sjob[tid]  = j;
        sword[tid] = (j >= 0) ? leaf_idx[j] : -1;
    }
    __syncthreads();

    // gather embedding rows (zeros for inactive jobs)
    for (int idx = tid; idx < TB * IN_; idx += blockDim.x) {
        int l = idx / IN_;
        int t = idx - l * IN_;
        int w = sword[l];
        sx[idx] = (w >= 0) ? embed[(size_t)w * IN_ + t] : 0.0f;
    }
    __syncthreads();

    if (tid < M_) {
        float ai[TB], ao[TB], au[TB];
        #pragma unroll
        for (int l = 0; l < TB; l++) { ai[l] = 0.f; ao[l] = 0.f; au[l] = 0.f; }

        #pragma unroll 2
        for (int t = 0; t < IN_; t++) {
            float w0 = __ldg(Wl + (size_t)t * G3_ + tid);
            float w1 = __ldg(Wl + (size_t)t * G3_ + M_ + tid);
            float w2 = __ldg(Wl + (size_t)t * G3_ + 2 * M_ + tid);
            #pragma unroll
            for (int l = 0; l < TB; l++) {
                float xv = sx[l * IN_ + t];
                ai[l] = fmaf(xv, w0, ai[l]);
                ao[l] = fmaf(xv, w1, ao[l]);
                au[l] = fmaf(xv, w2, au[l]);
            }
        }
        const float bi = bl[tid], bo = bl[M_ + tid], bu = bl[2 * M_ + tid];
        #pragma unroll
        for (int l = 0; l < TB; l++) {
            float* pc = g_c + (size_t)(jb + l) * M_ + tid;
            float* ph = g_h + (size_t)(jb + l) * M_ + tid;
            if (sjob[l] < 0) {
                *pc = 0.0f; *ph = 0.0f;
            } else {
                float i_ = sigm(ai[l] + bi);
                float o_ = sigm(ao[l] + bo);
                float u_ = tanhf(au[l] + bu);
                float c  = i_ * u_;
                float h  = o_ * tanhf(c);
                *pc = c; *ph = h;
            }
        }
    }
}

// ---------------------------------------------------------------------------
// Kernel C: dep-node cell for ctx elements of type 2.
// Block handles TC=8 ctx elements; 150 compute threads (one per M-lane).
// ---------------------------------------------------------------------------
__global__ void __launch_bounds__(160, 2)
dep_kernel(const float* __restrict__ embed,
           const float* __restrict__ Wiou,
           const float* __restrict__ Uiou,
           const float* __restrict__ biou,
           const float* __restrict__ Wf,
           const float* __restrict__ Uf,
           const float* __restrict__ bf,
           float* __restrict__ out) {
    __shared__ float sxd[TC * IN_];          // 9600 floats
    __shared__ float sh [TC * K_ * M_];      // 4800 floats
    __shared__ float shs[TC * M_];           // 1200 floats
    __shared__ int   styp[TC];
    __shared__ int   sword[TC];

    const int eb  = blockIdx.x * TC;
    const int tid = threadIdx.x;

    if (tid < TC) {
        styp[tid]  = g_type[eb + tid];
        sword[tid] = g_word[eb + tid];
    }
    __syncthreads();

    // load word embeddings
    for (int idx = tid; idx < TC * IN_; idx += blockDim.x) {
        int l = idx / IN_;
        int t = idx - l * IN_;
        sxd[idx] = (styp[l] == 2) ? embed[(size_t)sword[l] * IN_ + t] : 0.0f;
    }
    // load child h states
    for (int idx = tid; idx < TC * K_ * M_; idx += blockDim.x) {
        int l = idx / (K_ * M_);
        int r = idx - l * (K_ * M_);
        int k = r / M_;
        int t = r - k * M_;
        sh[idx] = (styp[l] == 2) ? g_h[((size_t)(eb + l) * 5 + 1 + k) * M_ + t] : 0.0f;
    }
    __syncthreads();
    // child-sum
    for (int idx = tid; idx < TC * M_; idx += blockDim.x) {
        int l = idx / M_;
        int t = idx - l * M_;
        shs[idx] = sh[(l * K_ + 0) * M_ + t] + sh[(l * K_ + 1) * M_ + t]
                 + sh[(l * K_ + 2) * M_ + t] + sh[(l * K_ + 3) * M_ + t];
    }
    __syncthreads();

    if (tid < M_) {
        float ai[TC], ao[TC], au[TC], axf[TC];
        float af[TC][K_];
        #pragma unroll
        for (int l = 0; l < TC; l++) {
            ai[l] = 0.f; ao[l] = 0.f; au[l] = 0.f; axf[l] = 0.f;
            #pragma unroll
            for (int k = 0; k < K_; k++) af[l][k] = 0.f;
        }

        // x-side: xd @ W_iou (3 gates) and xd @ W_f
        for (int t = 0; t < IN_; t++) {
            float wi = __ldg(Wiou + (size_t)t * G3_ + tid);
            float wo = __ldg(Wiou + (size_t)t * G3_ + M_ + tid);
            float wu = __ldg(Wiou + (size_t)t * G3_ + 2 * M_ + tid);
            float wf = __ldg(Wf   + (size_t)t * M_ + tid);
            #pragma unroll
            for (int l = 0; l < TC; l++) {
                float xv = sxd[l * IN_ + t];
                ai[l]  = fmaf(xv, wi, ai[l]);
                ao[l]  = fmaf(xv, wo, ao[l]);
                au[l]  = fmaf(xv, wu, au[l]);
                axf[l] = fmaf(xv, wf, axf[l]);
            }
        }
        // h-side: h_sum @ U_iou and per-child h_k @ U_f
        for (int t = 0; t < M_; t++) {
            float ui = __ldg(Uiou + (size_t)t * G3_ + tid);
            float uo = __ldg(Uiou + (size_t)t * G3_ + M_ + tid);
            float uu = __ldg(Uiou + (size_t)t * G3_ + 2 * M_ + tid);
            float uf = __ldg(Uf   + (size_t)t * M_ + tid);
            #pragma unroll
            for (int l = 0; l < TC; l++) {
                float hv = shs[l * M_ + t];
                ai[l] = fmaf(hv, ui, ai[l]);
                ao[l] = fmaf(hv, uo, ao[l]);
                au[l] = fmaf(hv, uu, au[l]);
                #pragma unroll
                for (int k = 0; k < K_; k++)
                    af[l][k] = fmaf(sh[(l * K_ + k) * M_ + t], uf, af[l][k]);
            }
        }

        const float bi = biou[tid], bo = biou[M_ + tid], bu = biou[2 * M_ + tid];
        const float bff = bf[tid];
        #pragma unroll
        for (int l = 0; l < TC; l++) {
            if (styp[l] != 2) continue;
            int e = eb + l;
            float i_ = sigm(ai[l] + bi);
            float o_ = sigm(ao[l] + bo);
            float u_ = tanhf(au[l] + bu);
            float c  = i_ * u_;
            #pragma unroll
            for (int k = 0; k < K_; k++) {
                float f  = sigm(axf[l] + af[l][k] + bff);
                float cc = g_c[((size_t)e * 5 + 1 + k) * M_ + tid];
                c = fmaf(f, cc, c);
            }
            float h = o_ * tanhf(c);
            out[(size_t)e * M_ + tid] = c;                          // c half
            out[(size_t)NCTX * M_ + (size_t)e * M_ + tid] = h;      // h half
        }
    }
}

// ---------------------------------------------------------------------------
// Kernel D: leaf-type and zero-type ctx elements (dep handled by kernel C)
// ---------------------------------------------------------------------------
__global__ void finish_kernel(float* __restrict__ out) {
    int idx = blockIdx.x * blockDim.x + threadIdx.x;   // over NCTX*M
    if (idx >= NCTX * M_) return;
    int e = idx / M_;
    int m = idx - e * M_;
    int t = g_type[e];
    if (t == 2) return;
    float c = 0.f, h = 0.f;
    if (t == 1) {
        c = g_c[(size_t)e * 5 * M_ + m];
        h = g_h[(size_t)e * 5 * M_ + m];
    }
    out[idx] = c;
    out[(size_t)NCTX * M_ + idx] = h;
}

// ---------------------------------------------------------------------------
extern "C" void kernel_launch(void* const* d_in, const int* in_sizes, int n_in,
                              void* d_out, int out_size) {
    const float* embed     = (const float*)d_in[0];
    const float* W_leaf    = (const float*)d_in[1];
    const float* b_leaf    = (const float*)d_in[2];
    const float* W_iou     = (const float*)d_in[3];
    const float* U_iou     = (const float*)d_in[4];
    const float* b_iou     = (const float*)d_in[5];
    const float* W_f       = (const float*)d_in[6];
    const float* U_f       = (const float*)d_in[7];
    const float* b_f       = (const float*)d_in[8];
    const int*   leaf_idx  = (const int*)d_in[9];
    const int*   dep_word  = (const int*)d_in[10];
    const int*   dep_child = (const int*)d_in[11];
    const int*   ctx_idx   = (const int*)d_in[12];
    float* out = (float*)d_out;

    build_jobs_kernel<<<(NCTX + 255) / 256, 256>>>(ctx_idx, dep_word, dep_child);
    leaf_kernel<<<NJOB / TB, 160>>>(embed, W_leaf, b_leaf, leaf_idx);
    dep_kernel<<<NCTX / TC, 160>>>(embed, W_iou, U_iou, b_iou, W_f, U_f, b_f, out);
    finish_kernel<<<(NCTX * M_ + 255) / 256, 256>>>(out);
}

// round 6
// speedup vs baseline: 1.2874x; 1.2874x over previous
#include <cuda_runtime.h>
#include <cuda_bf16.h>
#include <math.h>

// Problem constants
#define V_    50000
#define IN_   300
#define M_    150
#define G3_   450      // 3*M
#define NL_   200000
#define D_    6
#define N_    40000
#define K_    4
#define B_    64
#define S_    64
#define NCTX  (B_*S_)          // 4096
#define NJOB  (NCTX*5)         // 20480: slot e*5+0 = direct leaf, e*5+1..4 = children

#define TB 16            // leaf jobs per block (8 packed pairs)
#define PB (TB/2)
#define SXP 9            // padded pair-stride for leaf sx2 (bank-conflict pad)
#define TC 8             // ctx elements per dep block (4 packed pairs)
#define PC (TC/2)
#define SDP 5            // padded pair-stride for dep sxd2/shs2
#define SHP 21           // padded (k,pair) stride for dep sh2 (4*5+1)

// Scratch (device globals — no allocation allowed)
__device__ int   g_job[NJOB];          // leaf index (0..NL-1) or -1
__device__ int   g_type[NCTX];         // 0=zero slot, 1=leaf, 2=dep
__device__ int   g_word[NCTX];         // word idx for dep elements
__device__ float g_c[(size_t)NJOB * M_];
__device__ float g_h[(size_t)NJOB * M_];

__device__ __forceinline__ float sigm(float x) { return 1.0f / (1.0f + expf(-x)); }

// ---- packed f32x2 helpers (Blackwell sm_100a+) -----------------------------
__device__ __forceinline__ unsigned long long pack2(float lo, float hi) {
    unsigned long long r;
    asm("mov.b64 %0, {%1, %2};" : "=l"(r) : "f"(lo), "f"(hi));
    return r;
}
__device__ __forceinline__ void unpack2(unsigned long long v, float& lo, float& hi) {
    asm("mov.b64 {%0, %1}, %2;" : "=f"(lo), "=f"(hi) : "l"(v));
}
__device__ __forceinline__ unsigned long long fma2(unsigned long long a,
                                                   unsigned long long b,
                                                   unsigned long long c) {
    unsigned long long d;
    asm("fma.rn.f32x2 %0, %1, %2, %3;" : "=l"(d) : "l"(a), "l"(b), "l"(c));
    return d;
}
__device__ __forceinline__ unsigned long long add2(unsigned long long a,
                                                   unsigned long long b) {
    unsigned long long d;
    asm("add.rn.f32x2 %0, %1, %2;" : "=l"(d) : "l"(a), "l"(b));
    return d;
}

// ---------------------------------------------------------------------------
// Kernel A: classify each ctx element, build the leaf-job list
// ---------------------------------------------------------------------------
__global__ void build_jobs_kernel(const int* __restrict__ ctx,
                                  const int* __restrict__ dep_word,
                                  const int* __restrict__ dep_child) {
    int e = blockIdx.x * blockDim.x + threadIdx.x;
    if (e >= NCTX) return;
    int s = ctx[e];
    int base = e * 5;
    int j[5] = {-1, -1, -1, -1, -1};
    int type = 0, word = 0;
    if (s == 0) {
        type = 0;
    } else if (s <= NL_) {
        type = 1;
        j[0] = s - 1;
    } else {
        type = 2;
        int node = s - 1 - NL_;          // 0 .. D*N-1
        word = dep_word[node];
        #pragma unroll
        for (int k = 0; k < K_; k++) {
            int cs = dep_child[node * K_ + k];   // slot in [1, 1+NL)
            j[1 + k] = (cs >= 1 && cs <= NL_) ? (cs - 1) : -1;
        }
    }
    #pragma unroll
    for (int q = 0; q < 5; q++) g_job[base + q] = j[q];
    g_type[e] = type;
    g_word[e] = word;
}

// ---------------------------------------------------------------------------
// Kernel B: leaf cell, pair-packed f32x2 accumulation.
// Block = TB=16 jobs (8 pairs); 150 compute threads (one per M-lane).
// ---------------------------------------------------------------------------
__global__ void __launch_bounds__(160, 4)
leaf_kernel(const float* __restrict__ embed,
            const float* __restrict__ Wl,
            const float* __restrict__ bl,
            const int*   __restrict__ leaf_idx) {
    __shared__ float2 sx2[IN_ * SXP];   // [t][pair] pair-packed x, padded
    __shared__ int    sjob[TB];
    __shared__ int    sword[TB];

    const int jb  = blockIdx.x * TB;
    const int tid = threadIdx.x;

    if (tid < TB) {
        int j = g_job[jb + tid];
        sjob[tid]  = j;
        sword[tid] = (j >= 0) ? leaf_idx[j] : -1;
    }
    __syncthreads();

    // fill pair-packed x: thread handles (pair p, time t), two gathered loads
    for (int idx = tid; idx < PB * IN_; idx += blockDim.x) {
        int p = idx / IN_;
        int t = idx - p * IN_;
        int w0 = sword[2 * p], w1 = sword[2 * p + 1];
        float a = (w0 >= 0) ? embed[(size_t)w0 * IN_ + t] : 0.0f;
        float b = (w1 >= 0) ? embed[(size_t)w1 * IN_ + t] : 0.0f;
        sx2[t * SXP + p] = make_float2(a, b);
    }
    __syncthreads();

    if (tid < M_) {
        unsigned long long ai[PB], ao[PB], au[PB];
        #pragma unroll
        for (int p = 0; p < PB; p++) { ai[p] = 0ull; ao[p] = 0ull; au[p] = 0ull; }

        const unsigned long long* sx64 =
            reinterpret_cast<const unsigned long long*>(sx2);

        #pragma unroll 2
        for (int t = 0; t < IN_; t++) {
            float w0 = __ldg(Wl + (size_t)t * G3_ + tid);
            float w1 = __ldg(Wl + (size_t)t * G3_ + M_ + tid);
            float w2 = __ldg(Wl + (size_t)t * G3_ + 2 * M_ + tid);
            unsigned long long w0p = pack2(w0, w0);
            unsigned long long w1p = pack2(w1, w1);
            unsigned long long w2p = pack2(w2, w2);
            #pragma unroll
            for (int p = 0; p < PB; p++) {
                unsigned long long xv = sx64[t * SXP + p];   // LDS.64 broadcast
                ai[p] = fma2(xv, w0p, ai[p]);
                ao[p] = fma2(xv, w1p, ao[p]);
                au[p] = fma2(xv, w2p, au[p]);
            }
        }
        const float bi = bl[tid], bo = bl[M_ + tid], bu = bl[2 * M_ + tid];
        #pragma unroll
        for (int p = 0; p < PB; p++) {
            float i0, i1, o0, o1, u0, u1;
            unpack2(ai[p], i0, i1);
            unpack2(ao[p], o0, o1);
            unpack2(au[p], u0, u1);
            #pragma unroll
            for (int half = 0; half < 2; half++) {
                int l = 2 * p + half;
                float av = half ? i1 : i0;
                float bv = half ? o1 : o0;
                float cv = half ? u1 : u0;
                float* pc = g_c + (size_t)(jb + l) * M_ + tid;
                float* ph = g_h + (size_t)(jb + l) * M_ + tid;
                if (sjob[l] < 0) {
                    *pc = 0.0f; *ph = 0.0f;
                } else {
                    float i_ = sigm(av + bi);
                    float o_ = sigm(bv + bo);
                    float u_ = tanhf(cv + bu);
                    float c  = i_ * u_;
                    float h  = o_ * tanhf(c);
                    *pc = c; *ph = h;
                }
            }
        }
    }
}

// ---------------------------------------------------------------------------
// Kernel C: dep-node cell, pair-packed f32x2.
// Block = TC=8 ctx elements (4 pairs); 150 compute threads.
// ---------------------------------------------------------------------------
__global__ void __launch_bounds__(160, 2)
dep_kernel(const float* __restrict__ embed,
           const float* __restrict__ Wiou,
           const float* __restrict__ Uiou,
           const float* __restrict__ biou,
           const float* __restrict__ Wf,
           const float* __restrict__ Uf,
           const float* __restrict__ bf,
           float* __restrict__ out) {
    __shared__ float2 sxd2[IN_ * SDP];        // [t][pair] word x
    __shared__ float2 sh2 [M_ * SHP];         // [t][k][pair] child h
    __shared__ float2 shs2[M_ * SDP];         // [t][pair] child-sum h
    __shared__ int    styp[TC];
    __shared__ int    sword[TC];

    const int eb  = blockIdx.x * TC;
    const int tid = threadIdx.x;

    if (tid < TC) {
        styp[tid]  = g_type[eb + tid];
        sword[tid] = g_word[eb + tid];
    }
    __syncthreads();

    // pair-packed word embeddings
    for (int idx = tid; idx < PC * IN_; idx += blockDim.x) {
        int p = idx / IN_;
        int t = idx - p * IN_;
        int l0 = 2 * p, l1 = 2 * p + 1;
        float a = (styp[l0] == 2) ? embed[(size_t)sword[l0] * IN_ + t] : 0.0f;
        float b = (styp[l1] == 2) ? embed[(size_t)sword[l1] * IN_ + t] : 0.0f;
        sxd2[t * SDP + p] = make_float2(a, b);
    }
    // pair-packed child h
    for (int idx = tid; idx < PC * K_ * M_; idx += blockDim.x) {
        int pk = idx / M_;
        int t  = idx - pk * M_;
        int p  = pk / K_;
        int k  = pk - p * K_;
        int l0 = 2 * p, l1 = 2 * p + 1;
        float a = (styp[l0] == 2) ? g_h[((size_t)(eb + l0) * 5 + 1 + k) * M_ + t] : 0.0f;
        float b = (styp[l1] == 2) ? g_h[((size_t)(eb + l1) * 5 + 1 + k) * M_ + t] : 0.0f;
        sh2[t * SHP + k * PC + p] = make_float2(a, b);
    }
    __syncthreads();
    // pair-packed child-sum
    for (int idx = tid; idx < PC * M_; idx += blockDim.x) {
        int p = idx / M_;
        int t = idx - p * M_;
        const unsigned long long* s64 =
            reinterpret_cast<const unsigned long long*>(sh2);
        unsigned long long s = add2(add2(s64[t * SHP + 0 * PC + p],
                                         s64[t * SHP + 1 * PC + p]),
                                    add2(s64[t * SHP + 2 * PC + p],
                                         s64[t * SHP + 3 * PC + p]));
        reinterpret_cast<unsigned long long*>(shs2)[t * SDP + p] = s;
    }
    __syncthreads();

    if (tid < M_) {
        unsigned long long ai[PC], ao[PC], au[PC], axf[PC], af[PC][K_];
        #pragma unroll
        for (int p = 0; p < PC; p++) {
            ai[p] = 0ull; ao[p] = 0ull; au[p] = 0ull; axf[p] = 0ull;
            #pragma unroll
            for (int k = 0; k < K_; k++) af[p][k] = 0ull;
        }

        const unsigned long long* sxd64 =
            reinterpret_cast<const unsigned long long*>(sxd2);
        const unsigned long long* sh64 =
            reinterpret_cast<const unsigned long long*>(sh2);
        const unsigned long long* shs64 =
            reinterpret_cast<const unsigned long long*>(shs2);

        // x-side: xd @ W_iou (3 gates) and xd @ W_f
        #pragma unroll 2
        for (int t = 0; t < IN_; t++) {
            float wi = __ldg(Wiou + (size_t)t * G3_ + tid);
            float wo = __ldg(Wiou + (size_t)t * G3_ + M_ + tid);
            float wu = __ldg(Wiou + (size_t)t * G3_ + 2 * M_ + tid);
            float wf = __ldg(Wf   + (size_t)t * M_ + tid);
            unsigned long long wip = pack2(wi, wi);
            unsigned long long wop = pack2(wo, wo);
            unsigned long long wup = pack2(wu, wu);
            unsigned long long wfp = pack2(wf, wf);
            #pragma unroll
            for (int p = 0; p < PC; p++) {
                unsigned long long xv = sxd64[t * SDP + p];
                ai[p]  = fma2(xv, wip, ai[p]);
                ao[p]  = fma2(xv, wop, ao[p]);
                au[p]  = fma2(xv, wup, au[p]);
                axf[p] = fma2(xv, wfp, axf[p]);
            }
        }
        // h-side: h_sum @ U_iou and per-child h_k @ U_f
        #pragma unroll 2
        for (int t = 0; t < M_; t++) {
            float ui = __ldg(Uiou + (size_t)t * G3_ + tid);
            float uo = __ldg(Uiou + (size_t)t * G3_ + M_ + tid);
            float uu = __ldg(Uiou + (size_t)t * G3_ + 2 * M_ + tid);
            float uf = __ldg(Uf   + (size_t)t * M_ + tid);
            unsigned long long uip = pack2(ui, ui);
            unsigned long long uop = pack2(uo, uo);
            unsigned long long uup = pack2(uu, uu);
            unsigned long long ufp = pack2(uf, uf);
            #pragma unroll
            for (int p = 0; p < PC; p++) {
                unsigned long long hv = shs64[t * SDP + p];
                ai[p] = fma2(hv, uip, ai[p]);
                ao[p] = fma2(hv, uop, ao[p]);
                au[p] = fma2(hv, uup, au[p]);
                #pragma unroll
                for (int k = 0; k < K_; k++)
                    af[p][k] = fma2(sh64[t * SHP + k * PC + p], ufp, af[p][k]);
            }
        }

        const float bi = biou[tid], bo = biou[M_ + tid], bu = biou[2 * M_ + tid];
        const float bff = bf[tid];
        #pragma unroll
        for (int p = 0; p < PC; p++) {
            float i0, i1, o0, o1, u0, u1, x0, x1;
            unpack2(ai[p], i0, i1);
            unpack2(ao[p], o0, o1);
            unpack2(au[p], u0, u1);
            unpack2(axf[p], x0, x1);
            float f0[K_], f1[K_];
            #pragma unroll
            for (int k = 0; k < K_; k++) unpack2(af[p][k], f0[k], f1[k]);
            #pragma unroll
            for (int half = 0; half < 2; half++) {
                int l = 2 * p + half;
                if (styp[l] != 2) continue;
                int e = eb + l;
                float i_ = sigm((half ? i1 : i0) + bi);
                float o_ = sigm((half ? o1 : o0) + bo);
                float u_ = tanhf((half ? u1 : u0) + bu);
                float xf = half ? x1 : x0;
                float c  = i_ * u_;
                #pragma unroll
                for (int k = 0; k < K_; k++) {
                    float f  = sigm(xf + (half ? f1[k] : f0[k]) + bff);
                    float cc = g_c[((size_t)e * 5 + 1 + k) * M_ + tid];
                    c = fmaf(f, cc, c);
                }
                float h = o_ * tanhf(c);
                out[(size_t)e * M_ + tid] = c;                          // c half
                out[(size_t)NCTX * M_ + (size_t)e * M_ + tid] = h;      // h half
            }
        }
    }
}

// ---------------------------------------------------------------------------
// Kernel D: leaf-type and zero-type ctx elements (dep handled by kernel C)
// ---------------------------------------------------------------------------
__global__ void finish_kernel(float* __restrict__ out) {
    int idx = blockIdx.x * blockDim.x + threadIdx.x;   // over NCTX*M
    if (idx >= NCTX * M_) return;
    int e = idx / M_;
    int m = idx - e * M_;
    int t = g_type[e];
    if (t == 2) return;
    float c = 0.f, h = 0.f;
    if (t == 1) {
        c = g_c[(size_t)e * 5 * M_ + m];
        h = g_h[(size_t)e * 5 * M_ + m];
    }
    out[idx] = c;
    out[(size_t)NCTX * M_ + idx] = h;
}

// ---------------------------------------------------------------------------
extern "C" void kernel_launch(void* const* d_in, const int* in_sizes, int n_in,
                              void* d_out, int out_size) {
    const float* embed     = (const float*)d_in[0];
    const float* W_leaf    = (const float*)d_in[1];
    const float* b_leaf    = (const float*)d_in[2];
    const float* W_iou     = (const float*)d_in[3];
    const float* U_iou     = (const float*)d_in[4];
    const float* b_iou     = (const float*)d_in[5];
    const float* W_f       = (const float*)d_in[6];
    const float* U_f       = (const float*)d_in[7];
    const float* b_f       = (const float*)d_in[8];
    const int*   leaf_idx  = (const int*)d_in[9];
    const int*   dep_word  = (const int*)d_in[10];
    const int*   dep_child = (const int*)d_in[11];
    const int*   ctx_idx   = (const int*)d_in[12];
    float* out = (float*)d_out;

    build_jobs_kernel<<<(NCTX + 255) / 256, 256>>>(ctx_idx, dep_word, dep_child);
    leaf_kernel<<<NJOB / TB, 160>>>(embed, W_leaf, b_leaf, leaf_idx);
    dep_kernel<<<NCTX / TC, 160>>>(embed, W_iou, U_iou, b_iou, W_f, U_f, b_f, out);
    finish_kernel<<<(NCTX * M_ + 255) / 256, 256>>>(out);
}

// round 8
// speedup vs baseline: 1.2917x; 1.0033x over previous
#include <cuda_runtime.h>
#include <cuda_bf16.h>
#include <math.h>

// Problem constants
#define V_    50000
#define IN_   300
#define M_    150
#define G3_   450      // 3*M
#define NL_   200000
#define D_    6
#define N_    40000
#define K_    4
#define B_    64
#define S_    64
#define NCTX  (B_*S_)          // 4096
#define NJOB  (NCTX*5)         // 20480: slot e*5+0 = direct leaf, e*5+1..4 = children

#define TB 16            // leaf jobs per block (8 packed pairs)
#define PB (TB/2)
#define SXP 10           // pair-stride for leaf sx2: 80B rows, 16B aligned
#define TC 8             // ctx elements per dep block (4 packed pairs)
#define PC (TC/2)
#define SDP 4            // pair-stride for dep sxd2/shs2: 32B rows, 16B aligned, no pad
#define SHT 4            // per-t pair-stride inside sh2 [k][t][p]: 32B rows

// Scratch (device globals — no allocation allowed)
__device__ int   g_job[NJOB];          // leaf index (0..NL-1) or -1
__device__ int   g_type[NCTX];         // 0=zero slot, 1=leaf, 2=dep
__device__ int   g_word[NCTX];         // word idx for dep elements
__device__ float g_c[(size_t)NJOB * M_];
__device__ float g_h[(size_t)NJOB * M_];

__device__ __forceinline__ float sigm(float x) { return 1.0f / (1.0f + expf(-x)); }

// ---- packed f32x2 helpers (Blackwell sm_100a+) -----------------------------
__device__ __forceinline__ unsigned long long pack2(float lo, float hi) {
    unsigned long long r;
    asm("mov.b64 %0, {%1, %2};" : "=l"(r) : "f"(lo), "f"(hi));
    return r;
}
__device__ __forceinline__ void unpack2(unsigned long long v, float& lo, float& hi) {
    asm("mov.b64 {%0, %1}, %2;" : "=f"(lo), "=f"(hi) : "l"(v));
}
__device__ __forceinline__ unsigned long long fma2(unsigned long long a,
                                                   unsigned long long b,
                                                   unsigned long long c) {
    unsigned long long d;
    asm("fma.rn.f32x2 %0, %1, %2, %3;" : "=l"(d) : "l"(a), "l"(b), "l"(c));
    return d;
}
__device__ __forceinline__ unsigned long long add2(unsigned long long a,
                                                   unsigned long long b) {
    unsigned long long d;
    asm("add.rn.f32x2 %0, %1, %2;" : "=l"(d) : "l"(a), "l"(b));
    return d;
}

// ---------------------------------------------------------------------------
// Kernel A: classify each ctx element, build the leaf-job list
// ---------------------------------------------------------------------------
__global__ void build_jobs_kernel(const int* __restrict__ ctx,
                                  const int* __restrict__ dep_word,
                                  const int* __restrict__ dep_child) {
    int e = blockIdx.x * blockDim.x + threadIdx.x;
    if (e >= NCTX) return;
    int s = ctx[e];
    int base = e * 5;
    int j[5] = {-1, -1, -1, -1, -1};
    int type = 0, word = 0;
    if (s == 0) {
        type = 0;
    } else if (s <= NL_) {
        type = 1;
        j[0] = s - 1;
    } else {
        type = 2;
        int node = s - 1 - NL_;          // 0 .. D*N-1
        word = dep_word[node];
        #pragma unroll
        for (int k = 0; k < K_; k++) {
            int cs = dep_child[node * K_ + k];   // slot in [1, 1+NL)
            j[1 + k] = (cs >= 1 && cs <= NL_) ? (cs - 1) : -1;
        }
    }
    #pragma unroll
    for (int q = 0; q < 5; q++) g_job[base + q] = j[q];
    g_type[e] = type;
    g_word[e] = word;
}

// ---------------------------------------------------------------------------
// Kernel B: leaf cell, pair-packed f32x2 accumulation, LDS.128 activation loads.
// Block = TB=16 jobs (8 pairs); 150 compute threads (one per M-lane).
// ---------------------------------------------------------------------------
__global__ void __launch_bounds__(160, 4)
leaf_kernel(const float* __restrict__ embed,
            const float* __restrict__ Wl,
            const float* __restrict__ bl,
            const int*   __restrict__ leaf_idx) {
    __shared__ __align__(16) float2 sx2[IN_ * SXP];   // [t][pair], 80B rows
    __shared__ int sjob[TB];
    __shared__ int sword[TB];

    const int jb  = blockIdx.x * TB;
    const int tid = threadIdx.x;

    if (tid < TB) {
        int j = g_job[jb + tid];
        sjob[tid]  = j;
        sword[tid] = (j >= 0) ? leaf_idx[j] : -1;
    }
    __syncthreads();

    // fill pair-packed x: thread handles (pair p, time t), two gathered loads
    for (int idx = tid; idx < PB * IN_; idx += blockDim.x) {
        int p = idx / IN_;
        int t = idx - p * IN_;
        int w0 = sword[2 * p], w1 = sword[2 * p + 1];
        float a = (w0 >= 0) ? embed[(size_t)w0 * IN_ + t] : 0.0f;
        float b = (w1 >= 0) ? embed[(size_t)w1 * IN_ + t] : 0.0f;
        sx2[t * SXP + p] = make_float2(a, b);
    }
    __syncthreads();

    if (tid < M_) {
        unsigned long long ai[PB], ao[PB], au[PB];
        #pragma unroll
        for (int p = 0; p < PB; p++) { ai[p] = 0ull; ao[p] = 0ull; au[p] = 0ull; }

        #pragma unroll 4
        for (int t = 0; t < IN_; t++) {
            float w0 = __ldg(Wl + (size_t)t * G3_ + tid);
            float w1 = __ldg(Wl + (size_t)t * G3_ + M_ + tid);
            float w2 = __ldg(Wl + (size_t)t * G3_ + 2 * M_ + tid);
            unsigned long long w0p = pack2(w0, w0);
            unsigned long long w1p = pack2(w1, w1);
            unsigned long long w2p = pack2(w2, w2);
            const ulonglong2* row =
                reinterpret_cast<const ulonglong2*>(sx2 + t * SXP);
            #pragma unroll
            for (int q = 0; q < PB / 2; q++) {       // 4 × LDS.128 (broadcast)
                ulonglong2 xv = row[q];              // pairs 2q, 2q+1
                ai[2*q]   = fma2(xv.x, w0p, ai[2*q]);
                ao[2*q]   = fma2(xv.x, w1p, ao[2*q]);
                au[2*q]   = fma2(xv.x, w2p, au[2*q]);
                ai[2*q+1] = fma2(xv.y, w0p, ai[2*q+1]);
                ao[2*q+1] = fma2(xv.y, w1p, ao[2*q+1]);
                au[2*q+1] = fma2(xv.y, w2p, au[2*q+1]);
            }
        }
        const float bi = bl[tid], bo = bl[M_ + tid], bu = bl[2 * M_ + tid];
        #pragma unroll
        for (int p = 0; p < PB; p++) {
            float i0, i1, o0, o1, u0, u1;
            unpack2(ai[p], i0, i1);
            unpack2(ao[p], o0, o1);
            unpack2(au[p], u0, u1);
            #pragma unroll
            for (int half = 0; half < 2; half++) {
                int l = 2 * p + half;
                float av = half ? i1 : i0;
                float bv = half ? o1 : o0;
                float cv = half ? u1 : u0;
                float* pc = g_c + (size_t)(jb + l) * M_ + tid;
                float* ph = g_h + (size_t)(jb + l) * M_ + tid;
                if (sjob[l] < 0) {
                    *pc = 0.0f; *ph = 0.0f;
                } else {
                    float i_ = sigm(av + bi);
                    float o_ = sigm(bv + bo);
                    float u_ = tanhf(cv + bu);
                    float c  = i_ * u_;
                    float h  = o_ * tanhf(c);
                    *pc = c; *ph = h;
                }
            }
        }
    }
}

// ---------------------------------------------------------------------------
// Kernel C: dep-node cell, pair-packed f32x2, LDS.128 loads, occ 3.
// Block = TC=8 ctx elements (4 pairs); 150 compute threads.
// Static smem: 9600 + 19200 + 4800 + 64 B ≈ 33.7 KB (< 48 KB static limit)
// ---------------------------------------------------------------------------
__global__ void __launch_bounds__(160, 3)
dep_kernel(const float* __restrict__ embed,
           const float* __restrict__ Wiou,
           const float* __restrict__ Uiou,
           const float* __restrict__ biou,
           const float* __restrict__ Wf,
           const float* __restrict__ Uf,
           const float* __restrict__ bf,
           float* __restrict__ out) {
    __shared__ __align__(16) float2 sxd2[IN_ * SDP];       // [t][pair] word x
    __shared__ __align__(16) float2 sh2 [K_ * M_ * SHT];   // [k][t][pair] child h
    __shared__ __align__(16) float2 shs2[M_ * SDP];        // [t][pair] child-sum h
    __shared__ int styp[TC];
    __shared__ int sword[TC];

    const int eb  = blockIdx.x * TC;
    const int tid = threadIdx.x;

    if (tid < TC) {
        styp[tid]  = g_type[eb + tid];
        sword[tid] = g_word[eb + tid];
    }
    __syncthreads();

    // pair-packed word embeddings
    for (int idx = tid; idx < PC * IN_; idx += blockDim.x) {
        int p = idx / IN_;
        int t = idx - p * IN_;
        int l0 = 2 * p, l1 = 2 * p + 1;
        float a = (styp[l0] == 2) ? embed[(size_t)sword[l0] * IN_ + t] : 0.0f;
        float b = (styp[l1] == 2) ? embed[(size_t)sword[l1] * IN_ + t] : 0.0f;
        sxd2[t * SDP + p] = make_float2(a, b);
    }
    // pair-packed child h, [k][t][p]
    for (int idx = tid; idx < PC * K_ * M_; idx += blockDim.x) {
        int pk = idx / M_;
        int t  = idx - pk * M_;
        int p  = pk / K_;
        int k  = pk - p * K_;
        int l0 = 2 * p, l1 = 2 * p + 1;
        float a = (styp[l0] == 2) ? g_h[((size_t)(eb + l0) * 5 + 1 + k) * M_ + t] : 0.0f;
        float b = (styp[l1] == 2) ? g_h[((size_t)(eb + l1) * 5 + 1 + k) * M_ + t] : 0.0f;
        sh2[(k * M_ + t) * SHT + p] = make_float2(a, b);
    }
    __syncthreads();
    // pair-packed child-sum
    for (int idx = tid; idx < PC * M_; idx += blockDim.x) {
        int p = idx / M_;
        int t = idx - p * M_;
        const unsigned long long* s64 =
            reinterpret_cast<const unsigned long long*>(sh2);
        unsigned long long s = add2(add2(s64[(0 * M_ + t) * SHT + p],
                                         s64[(1 * M_ + t) * SHT + p]),
                                    add2(s64[(2 * M_ + t) * SHT + p],
                                         s64[(3 * M_ + t) * SHT + p]));
        reinterpret_cast<unsigned long long*>(shs2)[t * SDP + p] = s;
    }
    __syncthreads();

    if (tid < M_) {
        unsigned long long ai[PC], ao[PC], au[PC], axf[PC], af[PC][K_];
        #pragma unroll
        for (int p = 0; p < PC; p++) {
            ai[p] = 0ull; ao[p] = 0ull; au[p] = 0ull; axf[p] = 0ull;
            #pragma unroll
            for (int k = 0; k < K_; k++) af[p][k] = 0ull;
        }

        // x-side: xd @ W_iou (3 gates) and xd @ W_f
        #pragma unroll 2
        for (int t = 0; t < IN_; t++) {
            float wi = __ldg(Wiou + (size_t)t * G3_ + tid);
            float wo = __ldg(Wiou + (size_t)t * G3_ + M_ + tid);
            float wu = __ldg(Wiou + (size_t)t * G3_ + 2 * M_ + tid);
            float wf = __ldg(Wf   + (size_t)t * M_ + tid);
            unsigned long long wip = pack2(wi, wi);
            unsigned long long wop = pack2(wo, wo);
            unsigned long long wup = pack2(wu, wu);
            unsigned long long wfp = pack2(wf, wf);
            const ulonglong2* row =
                reinterpret_cast<const ulonglong2*>(sxd2 + t * SDP);
            ulonglong2 x01 = row[0];     // pairs 0,1
            ulonglong2 x23 = row[1];     // pairs 2,3
            unsigned long long xv[PC] = {x01.x, x01.y, x23.x, x23.y};
            #pragma unroll
            for (int p = 0; p < PC; p++) {
                ai[p]  = fma2(xv[p], wip, ai[p]);
                ao[p]  = fma2(xv[p], wop, ao[p]);
                au[p]  = fma2(xv[p], wup, au[p]);
                axf[p] = fma2(xv[p], wfp, axf[p]);
            }
        }
        // h-side: h_sum @ U_iou and per-child h_k @ U_f
        #pragma unroll 2
        for (int t = 0; t < M_; t++) {
            float ui = __ldg(Uiou + (size_t)t * G3_ + tid);
            float uo = __ldg(Uiou + (size_t)t * G3_ + M_ + tid);
            float uu = __ldg(Uiou + (size_t)t * G3_ + 2 * M_ + tid);
            float uf = __ldg(Uf   + (size_t)t * M_ + tid);
            unsigned long long uip = pack2(ui, ui);
            unsigned long long uop = pack2(uo, uo);
            unsigned long long uup = pack2(uu, uu);
            unsigned long long ufp = pack2(uf, uf);
            const ulonglong2* srow =
                reinterpret_cast<const ulonglong2*>(shs2 + t * SDP);
            ulonglong2 h01 = srow[0];
            ulonglong2 h23 = srow[1];
            unsigned long long hv[PC] = {h01.x, h01.y, h23.x, h23.y};
            #pragma unroll
            for (int p = 0; p < PC; p++) {
                ai[p] = fma2(hv[p], uip, ai[p]);
                ao[p] = fma2(hv[p], uop, ao[p]);
                au[p] = fma2(hv[p], uup, au[p]);
            }
            #pragma unroll
            for (int k = 0; k < K_; k++) {
                const ulonglong2* krow =
                    reinterpret_cast<const ulonglong2*>(sh2 + (k * M_ + t) * SHT);
                ulonglong2 k01 = krow[0];
                ulonglong2 k23 = krow[1];
                unsigned long long kv[PC] = {k01.x, k01.y, k23.x, k23.y};
                #pragma unroll
                for (int p = 0; p < PC; p++)
                    af[p][k] = fma2(kv[p], ufp, af[p][k]);
            }
        }

        const float bi = biou[tid], bo = biou[M_ + tid], bu = biou[2 * M_ + tid];
        const float bff = bf[tid];
        #pragma unroll
        for (int p = 0; p < PC; p++) {
            float i0, i1, o0, o1, u0, u1, x0, x1;
            unpack2(ai[p], i0, i1);
            unpack2(ao[p], o0, o1);
            unpack2(au[p], u0, u1);
            unpack2(axf[p], x0, x1);
            float f0[K_], f1[K_];
            #pragma unroll
            for (int k = 0; k < K_; k++) unpack2(af[p][k], f0[k], f1[k]);
            #pragma unroll
            for (int half = 0; half < 2; half++) {
                int l = 2 * p + half;
                if (styp[l] != 2) continue;
                int e = eb + l;
                float i_ = sigm((half ? i1 : i0) + bi);
                float o_ = sigm((half ? o1 : o0) + bo);
                float u_ = tanhf((half ? u1 : u0) + bu);
                float xf = half ? x1 : x0;
                float c  = i_ * u_;
                #pragma unroll
                for (int k = 0; k < K_; k++) {
                    float f  = sigm(xf + (half ? f1[k] : f0[k]) + bff);
                    float cc = g_c[((size_t)e * 5 + 1 + k) * M_ + tid];
                    c = fmaf(f, cc, c);
                }
                float h = o_ * tanhf(c);
                out[(size_t)e * M_ + tid] = c;                          // c half
                out[(size_t)NCTX * M_ + (size_t)e * M_ + tid] = h;      // h half
            }
        }
    }
}

// ---------------------------------------------------------------------------
// Kernel D: leaf-type and zero-type ctx elements (dep handled by kernel C)
// ---------------------------------------------------------------------------
__global__ void finish_kernel(float* __restrict__ out) {
    int idx = blockIdx.x * blockDim.x + threadIdx.x;   // over NCTX*M
    if (idx >= NCTX * M_) return;
    int e = idx / M_;
    int m = idx - e * M_;
    int t = g_type[e];
    if (t == 2) return;
    float c = 0.f, h = 0.f;
    if (t == 1) {
        c = g_c[(size_t)e * 5 * M_ + m];
        h = g_h[(size_t)e * 5 * M_ + m];
    }
    out[idx] = c;
    out[(size_t)NCTX * M_ + idx] = h;
}

// ---------------------------------------------------------------------------
extern "C" void kernel_launch(void* const* d_in, const int* in_sizes, int n_in,
                              void* d_out, int out_size) {
    const float* embed     = (const float*)d_in[0];
    const float* W_leaf    = (const float*)d_in[1];
    const float* b_leaf    = (const float*)d_in[2];
    const float* W_iou     = (const float*)d_in[3];
    const float* U_iou     = (const float*)d_in[4];
    const float* b_iou     = (const float*)d_in[5];
    const float* W_f       = (const float*)d_in[6];
    const float* U_f       = (const float*)d_in[7];
    const float* b_f       = (const float*)d_in[8];
    const int*   leaf_idx  = (const int*)d_in[9];
    const int*   dep_word  = (const int*)d_in[10];
    const int*   dep_child = (const int*)d_in[11];
    const int*   ctx_idx   = (const int*)d_in[12];
    float* out = (float*)d_out;

    build_jobs_kernel<<<(NCTX + 255) / 256, 256>>>(ctx_idx, dep_word, dep_child);
    leaf_kernel<<<NJOB / TB, 160>>>(embed, W_leaf, b_leaf, leaf_idx);
    dep_kernel<<<NCTX / TC, 160>>>(embed, W_iou, U_iou, b_iou, W_f, U_f, b_f, out);
    finish_kernel<<<(NCTX * M_ + 255) / 256, 256>>>(out);
}